// round 3
// baseline (speedup 1.0000x reference)
#include <cuda_runtime.h>

// SpixelNet_geom: mean over (B,N) of per-area masked variance.
// m = diff_round(diff_round(mask)); masked = img*m
// msum = sum(m)+EPS; mean = sum(masked)/msum
// varr = sum(((masked-mean)*m)^2)/msum ; out = mean(varr)
//
// Single-pass expansion:
//   sum(((g*m - mean)*m)^2) = S_c - 2*mean*S_b + mean^2*S_d
//   with S_m = sum(m), S_a = sum(g*m), S_b = sum(g*m^3),
//        S_c = sum(g^2*m^4), S_d = sum(m^2)

#define TWO_PI_F     6.28318530717958647692f
#define INV_TWO_PI_F 0.15915494309189533577f
#define EPS_F        1e-8f

__global__ void zero_out_kernel(float* out) { *out = 0.0f; }

// Block = 256 threads = 8 warps. Each warp holds two 16-lane segments;
// a segment handles one area (64 floats = 16 lanes x float4) per iteration.
// Each block covers 64 areas (4 iterations), then 1 atomicAdd.
__global__ __launch_bounds__(256, 8)
void area_loss_kernel(const float4* __restrict__ img4,
                      const float4* __restrict__ msk4,
                      float* __restrict__ out,
                      float scale) {
    const int tid  = threadIdx.x;
    const int warp = tid >> 5;
    const int lane = tid & 31;
    const int seg  = lane >> 4;   // 0 or 1: which area within the warp
    const int l16  = lane & 15;   // lane within the 16-lane segment

    float acc = 0.0f;
    // warp covers areas [blockBase + warp*8 + j*2 + seg], j = 0..3
    const int baseArea = (blockIdx.x << 6) + (warp << 3) + seg;

    #pragma unroll
    for (int j = 0; j < 4; ++j) {
        const int area = baseArea + (j << 1);
        const int idx  = area * 16 + l16;        // float4 index, 16 per area
        const float4 iv = img4[idx];
        const float4 mv = msk4[idx];

        float Sm = 0.f, Sa = 0.f, Sb = 0.f, Sc = 0.f, Sd = 0.f;
        const float gs[4] = {iv.x, iv.y, iv.z, iv.w};
        const float xs[4] = {mv.x, mv.y, mv.z, mv.w};

        #pragma unroll
        for (int e = 0; e < 4; ++e) {
            float x  = xs[e];
            float s1 = __sinf(TWO_PI_F * x);
            float y  = fmaf(-INV_TWO_PI_F, s1, x);   // diff_round(x)
            float s2 = __sinf(TWO_PI_F * y);
            float m  = fmaf(-INV_TWO_PI_F, s2, y);   // diff_round(diff_round(x))

            float g  = gs[e];
            float im = g * m;        // g*m
            float m2 = m * m;        // m^2
            float u  = im * m;       // g*m^2

            Sm += m;
            Sa += im;
            Sb = fmaf(im, m2, Sb);   // g*m^3
            Sc = fmaf(u,  u,  Sc);   // g^2*m^4
            Sd = fmaf(m,  m,  Sd);   // m^2
        }

        // 16-lane segmented reduction (xor offsets stay within the segment)
        #pragma unroll
        for (int off = 8; off >= 1; off >>= 1) {
            Sm += __shfl_xor_sync(0xffffffffu, Sm, off);
            Sa += __shfl_xor_sync(0xffffffffu, Sa, off);
            Sb += __shfl_xor_sync(0xffffffffu, Sb, off);
            Sc += __shfl_xor_sync(0xffffffffu, Sc, off);
            Sd += __shfl_xor_sync(0xffffffffu, Sd, off);
        }

        if (l16 == 0) {
            float msum = Sm + EPS_F;
            float mean = Sa / msum;
            float num  = fmaf(mean * mean, Sd, fmaf(-2.0f * mean, Sb, Sc));
            acc += num / msum;       // varr for this area
        }
    }

    // block-level reduction of the 16 segment-leader accumulators
    __shared__ float smem[16];
    if (l16 == 0) smem[(warp << 1) + seg] = acc;
    __syncthreads();

    if (tid < 16) {
        float v = smem[tid];
        #pragma unroll
        for (int off = 8; off >= 1; off >>= 1)
            v += __shfl_xor_sync(0x0000ffffu, v, off);
        if (tid == 0) atomicAdd(out, v * scale);
    }
}

extern "C" void kernel_launch(void* const* d_in, const int* in_sizes, int n_in,
                              void* d_out, int out_size) {
    const float* img = (const float*)d_in[0];   // sv_area_image [8,16384,8,8]
    const float* msk = (const float*)d_in[1];   // sv_area_mask  [8,16384,8,8]
    float* out = (float*)d_out;

    const int total  = in_sizes[0];      // 8*16384*64 = 8388608
    const int nAreas = total / 64;       // 131072
    const float scale = 1.0f / (float)nAreas;

    zero_out_kernel<<<1, 1>>>(out);

    const int blocks = nAreas / 64;      // 2048 blocks of 256 threads
    area_loss_kernel<<<blocks, 256>>>((const float4*)img,
                                      (const float4*)msk,
                                      out, scale);
}

// round 4
// speedup vs baseline: 1.1165x; 1.1165x over previous
#include <cuda_runtime.h>

// SpixelNet_geom: mean over (B,N) of per-area masked variance, single kernel.
// m = dr(dr(mask)); Sm=Σm, Sa=Σg·m, Sb=Σg·m³, Sc=Σg²·m⁴, Sd=Σm²
// varr = (Sc - 2·mean·Sb + mean²·Sd)/msum, mean = Sa/msum, msum = Sm+EPS.

#define TWO_PI_F     6.28318530717958647692f
#define INV_TWO_PI_F 0.15915494309189533577f
#define EPS_F        1e-8f

__device__ float    g_acc    = 0.0f;
__device__ unsigned g_ticket = 0u;

// 256 threads = 8 warps. Each 4-lane segment owns ONE area (64 floats):
// lane loads 4 float4s (16 elems) of its area, accumulates 5 sums in regs,
// then a 2-round width-4 shuffle reduction. 64 areas per block.
__global__ __launch_bounds__(256, 8)
void area_loss_kernel(const float4* __restrict__ img4,
                      const float4* __restrict__ msk4,
                      float* __restrict__ out,
                      float scale, unsigned nBlocks) {
    const int tid  = threadIdx.x;
    const int warp = tid >> 5;
    const int lane = tid & 31;
    const int seg  = lane >> 2;   // 0..7 : area within warp
    const int sub  = lane & 3;    // 0..3 : lane within 4-lane segment

    const int area = (blockIdx.x << 6) + (warp << 3) + seg;
    const int base = area * 16 + sub;       // float4 index

    // front-batch all 8 loads -> MLP = 8
    const float4 i0 = img4[base     ];
    const float4 i1 = img4[base +  4];
    const float4 i2 = img4[base +  8];
    const float4 i3 = img4[base + 12];
    const float4 m0 = msk4[base     ];
    const float4 m1 = msk4[base +  4];
    const float4 m2 = msk4[base +  8];
    const float4 m3 = msk4[base + 12];

    float Sm = 0.f, Sa = 0.f, Sb = 0.f, Sc = 0.f, Sd = 0.f;

    const float gs[16] = {i0.x,i0.y,i0.z,i0.w, i1.x,i1.y,i1.z,i1.w,
                          i2.x,i2.y,i2.z,i2.w, i3.x,i3.y,i3.z,i3.w};
    const float xs[16] = {m0.x,m0.y,m0.z,m0.w, m1.x,m1.y,m1.z,m1.w,
                          m2.x,m2.y,m2.z,m2.w, m3.x,m3.y,m3.z,m3.w};

    #pragma unroll
    for (int e = 0; e < 16; ++e) {
        float x  = xs[e];
        float s1 = __sinf(TWO_PI_F * x);
        float y  = fmaf(-INV_TWO_PI_F, s1, x);   // diff_round(x)
        float s2 = __sinf(TWO_PI_F * y);
        float m  = fmaf(-INV_TWO_PI_F, s2, y);   // diff_round(diff_round(x))

        float g  = gs[e];
        float im = g * m;        // g*m
        float m2 = m * m;        // m^2
        float u  = im * m;       // g*m^2

        Sm += m;
        Sa += im;
        Sb = fmaf(im, m2, Sb);   // g*m^3
        Sc = fmaf(u,  u,  Sc);   // g^2*m^4
        Sd = fmaf(m,  m,  Sd);   // m^2
    }

    // width-4 segmented reduction: 2 rounds x 5 values
    #pragma unroll
    for (int off = 2; off >= 1; off >>= 1) {
        Sm += __shfl_xor_sync(0xffffffffu, Sm, off);
        Sa += __shfl_xor_sync(0xffffffffu, Sa, off);
        Sb += __shfl_xor_sync(0xffffffffu, Sb, off);
        Sc += __shfl_xor_sync(0xffffffffu, Sc, off);
        Sd += __shfl_xor_sync(0xffffffffu, Sd, off);
    }

    // segment leader computes per-area variance
    float v = 0.0f;
    if (sub == 0) {
        float msum = Sm + EPS_F;
        float mean = Sa / msum;
        float num  = fmaf(mean * mean, Sd, fmaf(-2.0f * mean, Sb, Sc));
        v = num / msum;
    }

    // sum the 8 segment leaders across the warp (non-leaders hold 0)
    #pragma unroll
    for (int off = 4; off <= 16; off <<= 1)
        v += __shfl_xor_sync(0xffffffffu, v, off);

    __shared__ float smem[8];
    if (lane == 0) smem[warp] = v;
    __syncthreads();

    if (tid < 8) {
        float w = smem[tid];
        w += __shfl_xor_sync(0x000000ffu, w, 4);
        w += __shfl_xor_sync(0x000000ffu, w, 2);
        w += __shfl_xor_sync(0x000000ffu, w, 1);
        if (tid == 0) {
            atomicAdd(&g_acc, w);
            __threadfence();
            unsigned t = atomicAdd(&g_ticket, 1u);
            if (t == nBlocks - 1u) {           // last block finalizes
                *out     = g_acc * scale;
                g_acc    = 0.0f;               // reset for next graph replay
                g_ticket = 0u;
                __threadfence();
            }
        }
    }
}

extern "C" void kernel_launch(void* const* d_in, const int* in_sizes, int n_in,
                              void* d_out, int out_size) {
    const float* img = (const float*)d_in[0];   // sv_area_image [8,16384,8,8]
    const float* msk = (const float*)d_in[1];   // sv_area_mask  [8,16384,8,8]
    float* out = (float*)d_out;

    const int total  = in_sizes[0];      // 8*16384*64 = 8388608
    const int nAreas = total / 64;       // 131072
    const float scale = 1.0f / (float)nAreas;

    const unsigned blocks = (unsigned)(nAreas / 64);   // 2048
    area_loss_kernel<<<blocks, 256>>>((const float4*)img,
                                      (const float4*)msk,
                                      out, scale, blocks);
}